// round 12
// baseline (speedup 1.0000x reference)
#include <cuda_runtime.h>

#define BATCH 2048
#define TT    512
#define HID   64
#define NB    7       // rows per CTA (296 CTAs = exactly 2 per SM)
#define NCTA  296
#define NTHR  256

typedef unsigned long long u64;

__device__ __forceinline__ u64 ffma2(u64 a, u64 b, u64 c) {
    u64 d;
    asm("fma.rn.f32x2 %0, %1, %2, %3;" : "=l"(d) : "l"(a), "l"(b), "l"(c));
    return d;
}

__device__ __forceinline__ u64 add2(u64 a, u64 b) {
    u64 d;
    asm("add.rn.f32x2 %0, %1, %2;" : "=l"(d) : "l"(a), "l"(b));
    return d;
}

__device__ __forceinline__ float sum2(u64 v) {
    float lo, hi;
    asm("mov.b64 {%0, %1}, %2;" : "=f"(lo), "=f"(hi) : "l"(v));
    return lo + hi;
}

__device__ __forceinline__ float tanh_fast(float v) {
    float r;
    asm("tanh.approx.f32 %0, %1;" : "=f"(r) : "f"(v));
    return r;
}

__global__ __launch_bounds__(NTHR, 2)
void lstm_kernel(const float* __restrict__ x,
                 const float* __restrict__ W_ih,
                 const float* __restrict__ W_hh,
                 const float* __restrict__ b_ih,
                 const float* __restrict__ b_hh,
                 const float* __restrict__ W_d,
                 const float* __restrict__ b_d,
                 float* __restrict__ out) {
    __shared__ float x_s[NB][TT];        // 14 KB
    __shared__ float h_s[2][NB][HID];    // 3.5 KB, ping-pong on t parity

    const int tid  = threadIdx.x;
    const int lane = tid & 31;
    const int warp = tid >> 5;                 // 0..7
    const int q    = lane >> 3;                // gate id 0..3 (i,f,g,o)
    const int mu   = (warp << 3) | (lane & 7); // hidden unit 0..63 (warp-local block)
    const int col  = q * 64 + mu;              // full gate column owned by this lane
    // branchless activation: act(v) = s0 + s1*tanh(sc*v); gate 2 (g) is tanh
    const float s0 = (q == 2) ? 0.0f : 0.5f;
    const float s1 = (q == 2) ? 1.0f : 0.5f;
    const float sc = (q == 2) ? 1.0f : 0.5f;
    const bool isQ0 = (q == 0);

    const int row0 = blockIdx.x * NB;

    // --- weights: FULL column (64 floats = 32 u64 = 64 regs) ---
    u64 w2[32];
    {
        const ulonglong2* p = reinterpret_cast<const ulonglong2*>(W_hh + col * HID);
#pragma unroll
        for (int v = 0; v < 16; v++) {
            ulonglong2 u = p[v];
            w2[2 * v + 0] = u.x;
            w2[2 * v + 1] = u.y;
        }
    }
    const float bias = b_ih[col] + b_hh[col];
    const float wih  = W_ih[col];

    // --- stage x slab (coalesced; clamp rows past BATCH) ---
    for (int i = tid; i < NB * TT; i += NTHR) {
        int r = i / TT;
        int t = i % TT;
        int gr = row0 + r;
        if (gr > BATCH - 1) gr = BATCH - 1;
        x_s[r][t] = x[gr * TT + t];
    }
    for (int i = tid; i < NB * HID; i += NTHR)
        ((float*)h_s[0])[i] = 0.0f;

    // c state: q==0 lanes own c for (row, unit mu)
    float c[NB];
#pragma unroll
    for (int r = 0; r < NB; r++) c[r] = 0.0f;

    __syncthreads();

    for (int t = 0; t < TT; t++) {
        const float* hr = &h_s[t & 1][0][0];
        float*       hw = &h_s[(t + 1) & 1][0][0];

        // double-buffered quarter prefetch: buf index = (r*4+qt) & 1
        ulonglong2 buf[2][4];
#pragma unroll
        for (int v = 0; v < 4; v++)            // prologue: row 0, quarter 0
            buf[0][v] = *reinterpret_cast<const ulonglong2*>(hr + v * 4);

#pragma unroll
        for (int r = 0; r < NB; r++) {
            u64 aA = 0ull, aB = 0ull;
#pragma unroll
            for (int qt = 0; qt < 4; qt++) {
                const int slot = (r * 4 + qt) & 1;
                const int nxt  = r * 4 + qt + 1;
                if (nxt < NB * 4) {            // prefetch next quarter (full-warp broadcast)
                    const int nr = nxt >> 2, nq = nxt & 3;
#pragma unroll
                    for (int v = 0; v < 4; v++)
                        buf[slot ^ 1][v] = *reinterpret_cast<const ulonglong2*>(
                            hr + nr * HID + nq * 16 + v * 4);
                }
                // consume quarter qt: k in [qt*16, qt*16+16)
#pragma unroll
                for (int v = 0; v < 4; v++) {
                    const int b = qt * 8 + 2 * v;
                    if (qt & 1) {
                        aB = ffma2(w2[b + 0], buf[slot][v].x, aB);
                        aB = ffma2(w2[b + 1], buf[slot][v].y, aB);
                    } else {
                        aA = ffma2(w2[b + 0], buf[slot][v].x, aA);
                        aA = ffma2(w2[b + 1], buf[slot][v].y, aA);
                    }
                }
            }

            // full preactivation (no inter-lane reduce needed)
            float tot = fmaf(x_s[r][t], wih, bias) + sum2(add2(aA, aB));
            float act = fmaf(s1, tanh_fast(sc * tot), s0);

            // gather f,g,o to the q=0 lane: 3 independent shuffles (convergent)
            float r_f = __shfl_xor_sync(0xffffffffu, act, 8);
            float r_g = __shfl_xor_sync(0xffffffffu, act, 16);
            float r_o = __shfl_xor_sync(0xffffffffu, act, 24);

            if (isQ0) {   // act == i gate on these lanes
                c[r] = fmaf(r_f, c[r], act * r_g);
                hw[r * HID + mu] = r_o * tanh_fast(c[r]);
            }
        }
        __syncthreads();   // single barrier per step (double-buffered h)
    }

    // ---------- final projection: h_T is in buffer (TT & 1) == 0 ----------
    if (tid < NB && row0 + tid < BATCH) {
        float s = b_d[0];
#pragma unroll
        for (int mm = 0; mm < HID; mm++)
            s = fmaf(h_s[0][tid][mm], W_d[mm], s);
        out[row0 + tid] = s;
    }
}

extern "C" void kernel_launch(void* const* d_in, const int* in_sizes, int n_in,
                              void* d_out, int out_size) {
    const float* x    = (const float*)d_in[0];
    const float* W_ih = (const float*)d_in[1];
    const float* W_hh = (const float*)d_in[2];
    const float* b_ih = (const float*)d_in[3];
    const float* b_hh = (const float*)d_in[4];
    const float* W_d  = (const float*)d_in[5];
    const float* b_d  = (const float*)d_in[6];
    float* out = (float*)d_out;

    lstm_kernel<<<NCTA, NTHR>>>(x, W_ih, W_hh, b_ih, b_hh, W_d, b_d, out);
}

// round 13
// speedup vs baseline: 1.1626x; 1.1626x over previous
#include <cuda_runtime.h>

#define BATCH 2048
#define TT    512
#define HID   64
#define GATES 256     // 4*HID
#define NB    7       // rows per CTA (296 CTAs = exactly 2 per SM)
#define NCTA  296
#define NTHR  256

typedef unsigned long long u64;

__device__ __forceinline__ u64 ffma2(u64 a, u64 b, u64 c) {
    u64 d;
    asm("fma.rn.f32x2 %0, %1, %2, %3;" : "=l"(d) : "l"(a), "l"(b), "l"(c));
    return d;
}

__device__ __forceinline__ float sum2(u64 v) {
    float lo, hi;
    asm("mov.b64 {%0, %1}, %2;" : "=f"(lo), "=f"(hi) : "l"(v));
    return lo + hi;
}

__device__ __forceinline__ float tanh_fast(float v) {
    float r;
    asm("tanh.approx.f32 %0, %1;" : "=f"(r) : "f"(v));
    return r;
}

__global__ __launch_bounds__(NTHR, 2)
void lstm_kernel(const float* __restrict__ x,
                 const float* __restrict__ W_ih,
                 const float* __restrict__ W_hh,
                 const float* __restrict__ b_ih,
                 const float* __restrict__ b_hh,
                 const float* __restrict__ W_d,
                 const float* __restrict__ b_d,
                 float* __restrict__ out) {
    __shared__ float x_s[NB][TT];      // 14 KB
    __shared__ float h_s[NB][HID];     // 1.75 KB
    __shared__ float g_s[NB][GATES];   // 7 KB

    const int tid  = threadIdx.x;
    const int lane = tid & 31;
    const int warp = tid >> 5;                    // 0..7
    const int kh   = lane >> 4;                   // k-half: 0 -> k[0,32), 1 -> k[32,64)
    const int cp   = (warp << 4) | (lane & 15);   // column-pair id 0..127
    const int colA = cp;                          // i/f column (always sigmoid)
    const int colB = cp + 128;                    // g/o column
    const int mycol = kh ? colB : colA;           // column this thread finalizes
    const bool isTanh = (kh == 1) && (warp < 4);  // colB in g-range [128,192)
    // branchless activation: act(v) = s0 + s1*tanh(sc*v)
    const float s0 = isTanh ? 0.0f : 0.5f;
    const float s1 = isTanh ? 1.0f : 0.5f;
    const float sc = isTanh ? 1.0f : 0.5f;

    const int row0 = blockIdx.x * NB;

    // bank-conflict-avoiding chunk rotation: kh=1 processes its half starting
    // 16 floats in (k48..k63 then k32..k47), so each LDS.128 instruction's two
    // half-warps hit disjoint bank groups -> 1 wavefront instead of 2.
    const int khoff = kh * 32;
    const int rot   = kh * 16;

    // --- weights: k-half of both owned columns, loaded in the SAME rotated
    //     chunk order the h-loads will use (dot product terms just reordered) ---
    u64 wA[16], wB[16];
    {
        const ulonglong2* pa = reinterpret_cast<const ulonglong2*>(W_hh + colA * HID + khoff);
        const ulonglong2* pb = reinterpret_cast<const ulonglong2*>(W_hh + colB * HID + khoff);
#pragma unroll
        for (int c = 0; c < 8; c++) {
            int src = (c + 4 * kh) & 7;          // rotate by 4 chunks (16 floats) for kh=1
            ulonglong2 va = pa[src];
            wA[2 * c + 0] = va.x;  wA[2 * c + 1] = va.y;
            ulonglong2 vb = pb[src];
            wB[2 * c + 0] = vb.x;  wB[2 * c + 1] = vb.y;
        }
    }
    const float bias = b_ih[mycol] + b_hh[mycol];
    const float wih  = W_ih[mycol];

    // --- stage x slab (coalesced; clamp rows past BATCH) ---
    for (int i = tid; i < NB * TT; i += NTHR) {
        int r = i / TT;
        int t = i % TT;
        int gr = row0 + r;
        if (gr > BATCH - 1) gr = BATCH - 1;
        x_s[r][t] = x[gr * TT + t];
    }
    for (int i = tid; i < NB * HID; i += NTHR)
        ((float*)h_s)[i] = 0.0f;

    // --- phase-2 ownership: NB*HID = 448 cell states ---
    float c0 = 0.0f, c1 = 0.0f;
    const int r0a = tid >> 6,            m0 = tid & 63;
    const bool has1 = (tid < NB * HID - NTHR);   // tid < 192
    const int idx1 = tid + NTHR;
    const int r1a = idx1 >> 6,           m1 = idx1 & 63;

    __syncthreads();

    for (int t = 0; t < TT; t++) {
        // hoisted x loads for all rows (broadcast, MLP batch)
        float xv[NB];
#pragma unroll
        for (int r = 0; r < NB; r++) xv[r] = x_s[r][t];

        // ---------- phase 1: software-pipelined over rows (R8 shape) ----------
        ulonglong2 hva[4], hvb[4];
#pragma unroll
        for (int c = 0; c < 4; c++)        // prologue: row 0, chunk group 0 (rotated)
            hva[c] = *reinterpret_cast<const ulonglong2*>(
                &h_s[0][khoff + ((c * 4 + rot) & 31)]);

#pragma unroll
        for (int r = 0; r < NB; r++) {
            // load chunk group 1 of row r (rotated addresses)
#pragma unroll
            for (int c = 0; c < 4; c++)
                hvb[c] = *reinterpret_cast<const ulonglong2*>(
                    &h_s[r][khoff + (((c + 4) * 4 + rot) & 31)]);

            u64 aA = 0ull, aB = 0ull;
            // consume chunk group 0
#pragma unroll
            for (int c = 0; c < 4; c++) {
                aA = ffma2(wA[2 * c + 0], hva[c].x, aA);
                aA = ffma2(wA[2 * c + 1], hva[c].y, aA);
                aB = ffma2(wB[2 * c + 0], hva[c].x, aB);
                aB = ffma2(wB[2 * c + 1], hva[c].y, aB);
            }
            // prefetch chunk group 0 of row r+1 (overlaps group-1 FMAs below)
            if (r + 1 < NB) {
#pragma unroll
                for (int c = 0; c < 4; c++)
                    hva[c] = *reinterpret_cast<const ulonglong2*>(
                        &h_s[r + 1][khoff + ((c * 4 + rot) & 31)]);
            }
            // consume chunk group 1
#pragma unroll
            for (int c = 0; c < 4; c++) {
                aA = ffma2(wA[8 + 2 * c + 0], hvb[c].x, aA);
                aA = ffma2(wA[8 + 2 * c + 1], hvb[c].y, aA);
                aB = ffma2(wB[8 + 2 * c + 0], hvb[c].x, aB);
                aB = ffma2(wB[8 + 2 * c + 1], hvb[c].y, aB);
            }

            // reduce across k-half partner (lane ^ 16), convergent
            float pA = sum2(aA), pB = sum2(aB);
            float send = kh ? pA : pB;
            float recv = __shfl_xor_sync(0xffffffffu, send, 16);
            float own  = kh ? pB : pA;
            float tot  = fmaf(xv[r], wih, bias) + own + recv;
            g_s[r][mycol] = fmaf(s1, tanh_fast(sc * tot), s0);
        }
        __syncthreads();

        // ---------- phase 2: cell/hidden update (R8 verbatim) ----------
        {
            float i_ = g_s[r0a][m0];
            float f_ = g_s[r0a][64 + m0];
            float gg = g_s[r0a][128 + m0];
            float o_ = g_s[r0a][192 + m0];
            c0 = fmaf(f_, c0, i_ * gg);
            h_s[r0a][m0] = o_ * tanh_fast(c0);
        }
        if (has1) {
            float i_ = g_s[r1a][m1];
            float f_ = g_s[r1a][64 + m1];
            float gg = g_s[r1a][128 + m1];
            float o_ = g_s[r1a][192 + m1];
            c1 = fmaf(f_, c1, i_ * gg);
            h_s[r1a][m1] = o_ * tanh_fast(c1);
        }
        __syncthreads();
    }

    // ---------- final projection ----------
    if (tid < NB && row0 + tid < BATCH) {
        float s = b_d[0];
#pragma unroll
        for (int m = 0; m < HID; m++)
            s = fmaf(h_s[tid][m], W_d[m], s);
        out[row0 + tid] = s;
    }
}

extern "C" void kernel_launch(void* const* d_in, const int* in_sizes, int n_in,
                              void* d_out, int out_size) {
    const float* x    = (const float*)d_in[0];
    const float* W_ih = (const float*)d_in[1];
    const float* W_hh = (const float*)d_in[2];
    const float* b_ih = (const float*)d_in[3];
    const float* b_hh = (const float*)d_in[4];
    const float* W_d  = (const float*)d_in[5];
    const float* b_d  = (const float*)d_in[6];
    float* out = (float*)d_out;

    lstm_kernel<<<NCTA, NTHR>>>(x, W_ih, W_hh, b_ih, b_hh, W_d, b_d, out);
}